// round 9
// baseline (speedup 1.0000x reference)
#include <cuda_runtime.h>
#include <cstdint>

#define BATCH 128
#define NPRI  8732
#define NOBJ  16
#define NCLS  21
#define THRESH 0.5f
#define CEB    35       // 256-prior blocks per image (35*256 >= 8732)

// ---------------- scratch (static device globals; zero-initialized) ----------
__device__ float              g_btov[BATCH * NPRI];
__device__ uint8_t            g_bti [BATCH * NPRI];
__device__ uint8_t            g_ct  [BATCH * NPRI];
__device__ uint8_t            g_of  [BATCH * NPRI];
__device__ float              g_ce  [BATCH * NPRI];
__device__ unsigned long long g_best[BATCH * NOBJ];  // re-zeroed by k3 each launch
__device__ int                g_npos[BATCH];         // re-zeroed by k3 each launch
__device__ float              g_nposf[BATCH];
__device__ float              g_locs[BATCH];
__device__ float              g_pces[BATCH];
__device__ float              g_negs[BATCH];
__device__ unsigned int       g_ticket;              // reset by last block each launch

// ---------------- helpers -----------------------------------------------------
__device__ __forceinline__ float sl1(float x) {
    float a = fabsf(x);
    return (a < 1.f) ? 0.5f * a * a : a - 0.5f;
}

// two block-sums for the price of one barrier set; s must hold 64 floats
__device__ __forceinline__ float2 brSum2F(float a, float b, float* s) {
    int lane = threadIdx.x & 31, wid = threadIdx.x >> 5;
    int nw = (blockDim.x + 31) >> 5;
    #pragma unroll
    for (int o = 16; o; o >>= 1) {
        a += __shfl_xor_sync(0xFFFFFFFFu, a, o);
        b += __shfl_xor_sync(0xFFFFFFFFu, b, o);
    }
    if (lane == 0) { s[wid] = a; s[32 + wid] = b; }
    __syncthreads();
    if (wid == 0) {
        float ra = (lane < nw) ? s[lane] : 0.f;
        float rb = (lane < nw) ? s[32 + lane] : 0.f;
        #pragma unroll
        for (int o = 16; o; o >>= 1) {
            ra += __shfl_xor_sync(0xFFFFFFFFu, ra, o);
            rb += __shfl_xor_sync(0xFFFFFFFFu, rb, o);
        }
        if (lane == 0) { s[0] = ra; s[32] = rb; }
    }
    __syncthreads();
    float2 r = make_float2(s[0], s[32]);
    __syncthreads();
    return r;
}

// ---------------- K1: fused matching, shared-transpose per-truth reduce -------
// grid = BATCH*CEB, one thread = one prior. Hot loop: IoU + 1 STS per pair.
__global__ __launch_bounds__(256)
void k1_match(const float* __restrict__ boxes, const float* __restrict__ priors) {
    const int b    = blockIdx.x / CEB;
    const int t    = blockIdx.x % CEB;
    const int tid  = threadIdx.x;
    const int lane = tid & 31, wid = tid >> 5;
    const int p    = t * 256 + tid;
    const bool valid = (p < NPRI);

    __shared__ float4 s_t[NOBJ];
    __shared__ float  s_ta[NOBJ];
    __shared__ float  s_v[256][NOBJ + 1];   // pad 17: conflict-free write & read

    if (tid < NOBJ) {
        float4 tb = ((const float4*)boxes)[b * NOBJ + tid];
        s_t[tid]  = tb;
        s_ta[tid] = (tb.z - tb.x) * (tb.w - tb.y);
    }
    __syncthreads();

    // invalid tail threads use a far-away degenerate box: inter = 0 -> v = 0,
    // and their larger in-block index loses every tie (ties pick smallest p).
    float px1 = 2.f, py1 = 2.f, px2 = 2.f, py2 = 2.f, ap = 0.f;
    if (valid) {
        float4 pr = ((const float4*)priors)[p];
        float hw = 0.5f * pr.z, hh = 0.5f * pr.w;
        px1 = pr.x - hw; py1 = pr.y - hh; px2 = pr.x + hw; py2 = pr.y + hh;
        ap = pr.z * pr.w;
    }

    float pv = -1.f; int po = 0;
    #pragma unroll
    for (int o = 0; o < NOBJ; o++) {
        float4 tb = s_t[o];
        float ix = fmaxf(fminf(tb.z, px2) - fmaxf(tb.x, px1), 0.f);
        float iy = fmaxf(fminf(tb.w, py2) - fmaxf(tb.y, py1), 0.f);
        float inter = ix * iy;
        float den   = (s_ta[o] + ap) - inter;
        float v     = __fdividef(inter, den);   // approx: ordering only
        s_v[tid][o] = v;                        // per-truth reduce deferred
        bool g = v > pv;                        // first truth on tie
        pv = g ? v : pv;  po = g ? o : po;
    }

    if (valid) {
        // exact IoU for the winning truth only (threshold semantics exact)
        float4 tb = s_t[po];
        float ix = fmaxf(fminf(tb.z, px2) - fmaxf(tb.x, px1), 0.f);
        float iy = fmaxf(fminf(tb.w, py2) - fmaxf(tb.y, py1), 0.f);
        float inter = ix * iy;
        float den   = (s_ta[po] + ap) - inter;
        g_btov[b * NPRI + p] = inter / den;     // div.rn, once per prior
        g_bti [b * NPRI + p] = (uint8_t)po;
    }

    __syncthreads();

    // phase 2: 8 warps x 2 truths; column argmax (first index on tie)
    #pragma unroll
    for (int rep = 0; rep < 2; rep++) {
        const int o = wid + rep * 8;
        float bv = -1.f; int bi = 0;
        #pragma unroll
        for (int k = 0; k < 8; k++) {
            int i = lane + k * 32;
            float v = s_v[i][o];                // stride 17 words: conflict-free
            bool g = v > bv;                    // ascending i: keeps smallest i
            bv = g ? v : bv;  bi = g ? i : bi;
        }
        #pragma unroll
        for (int off = 16; off; off >>= 1) {    // exact (v, i) argmax reduce
            float ov = __shfl_xor_sync(0xFFFFFFFFu, bv, off);
            int   oi = __shfl_xor_sync(0xFFFFFFFFu, bi, off);
            bool take = (ov > bv) || (ov == bv && oi < bi);
            bv = take ? ov : bv;  bi = take ? oi : bi;
        }
        if (lane == 0) {
            unsigned pw = (unsigned)(t * 256 + bi);
            unsigned long long key =
                ((unsigned long long)__float_as_uint(bv) << 32) |
                (unsigned)(0xFFFFFFFFu - pw);   // tie -> smaller p wins
            atomicMax(&g_best[b * NOBJ + o], key);
        }
    }
}

// ---------------- K2: force-assign + conf target + cross entropy --------------
__global__ __launch_bounds__(256)
void k2_ce(const float* __restrict__ conf, const int* __restrict__ labels) {
    const int blk = blockIdx.x;
    const int b   = blk / CEB;
    const int t   = blk % CEB;
    const int tid = threadIdx.x;
    const int r0  = t * 256;
    const int nr  = min(256, NPRI - r0);

    __shared__ float    s_rows[256 * NCLS];
    __shared__ int      s_lab[NOBJ];
    __shared__ unsigned s_fp[NOBJ];
    __shared__ int      s_wc[8];

    if (tid < NOBJ) {
        s_lab[tid] = labels[b * NOBJ + tid];
        s_fp[tid]  = 0xFFFFFFFFu - (unsigned)(g_best[b * NOBJ + tid] & 0xFFFFFFFFULL);
    }
    const int nf4 = nr * NCLS / 4;
    const float4* src = (const float4*)(conf + ((size_t)b * NPRI + r0) * NCLS);
    #pragma unroll
    for (int i = 0; i < 6; i++) {
        int j = tid + i * 256;
        if (j < nf4) ((float4*)s_rows)[j] = src[j];
    }
    __syncthreads();

    int isp = 0;
    if (tid < nr) {
        int p = r0 + tid;
        size_t idx = (size_t)b * NPRI + p;
        float ov = g_btov[idx];
        int   o  = g_bti[idx];
        #pragma unroll
        for (int oo = 0; oo < NOBJ; oo++) {          // ascending: last truth wins
            bool f = (s_fp[oo] == (unsigned)p);
            ov = f ? 2.0f : ov;
            o  = f ? oo : o;
        }
        int ct = (ov < THRESH) ? 0 : (s_lab[o] + 1);
        g_ct[idx] = (uint8_t)ct;
        g_of[idx] = (uint8_t)o;
        isp = (ct > 0);
        const float* v = s_rows + tid * NCLS;        // stride 21: conflict-free
        float m = v[0];
        #pragma unroll
        for (int c = 1; c < NCLS; c++) m = fmaxf(m, v[c]);
        float ssum = 0.f;
        #pragma unroll
        for (int c = 0; c < NCLS; c++) ssum += __expf(v[c] - m);
        g_ce[idx] = m + __logf(ssum) - v[ct];
    }
    int c = __reduce_add_sync(0xFFFFFFFFu, isp);
    if ((tid & 31) == 0) s_wc[tid >> 5] = c;
    __syncthreads();
    if (tid == 0) {
        int cc = 0;
        #pragma unroll
        for (int w = 0; w < 8; w++) cc += s_wc[w];
        atomicAdd(&g_npos[b], cc);
    }
}

// ---------------- K3: loc loss + 2-bit radix top-K (1 bar/round) + final ------
__global__ __launch_bounds__(1024)
void k3_select(const float* __restrict__ loc_preds,
               const float* __restrict__ boxes,
               const float* __restrict__ priors,
               float* __restrict__ out) {
    const int b    = blockIdx.x;
    const int tid  = threadIdx.x;
    const int lane = tid & 31, wid = tid >> 5;

    __shared__ float s_tx1[NOBJ], s_ty1[NOBJ], s_tx2[NOBJ], s_ty2[NOBJ];
    __shared__ float s_redf[64];
    __shared__ int   s_cnt[2][3][32];   // double-buffered per-warp counts
    __shared__ int   s_bc[4];

    if (tid < NOBJ) {
        s_tx1[tid] = boxes[(b * NOBJ + tid) * 4 + 0];
        s_ty1[tid] = boxes[(b * NOBJ + tid) * 4 + 1];
        s_tx2[tid] = boxes[(b * NOBJ + tid) * 4 + 2];
        s_ty2[tid] = boxes[(b * NOBJ + tid) * 4 + 3];
    }
    const int npos = g_npos[b];          // uniform load by all threads
    __syncthreads();

    unsigned u[9];
    float posce = 0.f, locsum = 0.f;
    #pragma unroll
    for (int i = 0; i < 9; i++) {
        int p = tid + i * 1024;
        u[i] = 0u;
        if (p < NPRI) {
            size_t idx = (size_t)b * NPRI + p;
            float ce = g_ce[idx];
            if (g_ct[idx] > 0) {
                posce += ce;
                int o = g_of[idx];
                float4 pr = ((const float4*)priors)[p];
                float tx1 = s_tx1[o], ty1 = s_ty1[o], tx2 = s_tx2[o], ty2 = s_ty2[o];
                float g0 = ((tx1 + tx2) * 0.5f - pr.x) / (0.1f * pr.z);
                float g1 = ((ty1 + ty2) * 0.5f - pr.y) / (0.1f * pr.w);
                float g2 = __logf((tx2 - tx1) / pr.z) * 5.0f;
                float g3 = __logf((ty2 - ty1) / pr.w) * 5.0f;
                float4 lp = ((const float4*)loc_preds)[(size_t)b * NPRI + p];
                locsum += sl1(lp.x - g0) + sl1(lp.y - g1)
                        + sl1(lp.z - g2) + sl1(lp.w - g3);
            } else {
                u[i] = __float_as_uint(ce);   // negatives only; ce >= 0
            }
        }
    }

    float2 pl = brSum2F(posce, locsum, s_redf);
    const float pcT = pl.x, lcT = pl.y;

    int K = 3 * npos; if (K > NPRI) K = NPRI;
    float negsum = 0.f;
    if (K > 0) {
        unsigned prefix = 0u;
        int par = 0;
        // 15 rounds x 2 bits (bits 30..1); 1 barrier per round (double buffer)
        for (int sh = 29; sh >= 1; sh -= 2) {
            unsigned cA = prefix | (1u << sh);
            unsigned cB = prefix | (2u << sh);
            unsigned cC = prefix | (3u << sh);
            int n1 = 0, n2 = 0, n3 = 0;
            #pragma unroll
            for (int i = 0; i < 9; i++) {
                n1 += (u[i] >= cA);
                n2 += (u[i] >= cB);
                n3 += (u[i] >= cC);
            }
            n1 = __reduce_add_sync(0xFFFFFFFFu, n1);
            n2 = __reduce_add_sync(0xFFFFFFFFu, n2);
            n3 = __reduce_add_sync(0xFFFFFFFFu, n3);
            if (lane == 0) {
                s_cnt[par][0][wid] = n1;
                s_cnt[par][1][wid] = n2;
                s_cnt[par][2][wid] = n3;
            }
            __syncthreads();
            // every warp reduces the 32 partials redundantly (no 2nd barrier)
            int t1 = __reduce_add_sync(0xFFFFFFFFu, s_cnt[par][0][lane]);
            int t2 = __reduce_add_sync(0xFFFFFFFFu, s_cnt[par][1][lane]);
            int t3 = __reduce_add_sync(0xFFFFFFFFu, s_cnt[par][2][lane]);
            prefix |= (t3 >= K) ? (3u << sh)
                    : (t2 >= K) ? (2u << sh)
                    : (t1 >= K) ? (1u << sh) : 0u;
            par ^= 1;
        }
        {   // final bit 0
            unsigned cand = prefix | 1u;
            int n = 0;
            #pragma unroll
            for (int i = 0; i < 9; i++) n += (u[i] >= cand);
            n = __reduce_add_sync(0xFFFFFFFFu, n);
            if (lane == 0) s_cnt[par][0][wid] = n;
            __syncthreads();
            int tot = __reduce_add_sync(0xFFFFFFFFu, s_cnt[par][0][lane]);
            if (tot >= K) prefix |= 1u;
        }
        float vK = __uint_as_float(prefix);       // exact K-th largest
        float sgt = 0.f; int cgt = 0;
        #pragma unroll
        for (int i = 0; i < 9; i++) {
            float v = __uint_as_float(u[i]);
            if (v > vK) { sgt += v; cgt++; }
        }
        float2 sc = brSum2F(sgt, (float)cgt, s_redf);   // cgt < 2^24: exact
        negsum = sc.x + ((float)K - sc.y) * vK;         // ties handled exactly
    }

    if (tid == 0) {
        g_locs[b]  = lcT;
        g_pces[b]  = pcT;
        g_negs[b]  = negsum;
        g_nposf[b] = (float)npos;
    }
    if (tid < NOBJ) g_best[b * NOBJ + tid] = 0ULL;   // re-zero for graph replay
    if (tid == 32)  g_npos[b] = 0;

    __threadfence();
    __syncthreads();
    if (tid == 0) {
        unsigned old = atomicAdd(&g_ticket, 1u);
        s_bc[2] = (old == BATCH - 1) ? 1 : 0;
    }
    __syncthreads();

    if (s_bc[2]) {   // last block: final reduction over images
        float np = 0.f, lc = 0.f, pc = 0.f, ns = 0.f;
        if (tid < BATCH) {
            np = __ldcg(&g_nposf[tid]);
            lc = __ldcg(&g_locs[tid]);
            pc = __ldcg(&g_pces[tid]);
            ns = __ldcg(&g_negs[tid]);
        }
        float2 r1 = brSum2F(np, lc, s_redf);
        float2 r2 = brSum2F(pc, ns, s_redf);
        if (tid == 0) {
            out[0] = (r2.x + r2.y) / (r1.x + 1e-7f) + r1.y / (4.0f * r1.x);
            g_ticket = 0u;
        }
    }
}

// ---------------- launch ------------------------------------------------------
extern "C" void kernel_launch(void* const* d_in, const int* in_sizes, int n_in,
                              void* d_out, int out_size) {
    const float* loc_preds  = (const float*)d_in[0];
    const float* conf_preds = (const float*)d_in[1];
    const float* boxes      = (const float*)d_in[2];
    const int*   labels     = (const int*)d_in[3];
    const float* priors     = (const float*)d_in[4];
    float* out = (float*)d_out;

    k1_match<<<BATCH * CEB, 256>>>(boxes, priors);
    k2_ce<<<BATCH * CEB, 256>>>(conf_preds, labels);
    k3_select<<<BATCH, 1024>>>(loc_preds, boxes, priors, out);
    (void)in_sizes; (void)n_in; (void)out_size;
}